// round 15
// baseline (speedup 1.0000x reference)
#include <cuda_runtime.h>
#include <cuda_fp16.h>
#include <math.h>
#include <stdint.h>

// Problem constants
#define AA 512
#define BB 32
#define IDIM 256
#define HDIM 512
#define ODIM 1024          // MSG_DIM * VOCAB
#define NROWS (AA * BB)    // 16384
#define MAX_TILES 160

// d_out layout: [logits] [h_out] [c_out]
#define LOGITS_OFF 0
#define H_OFF (AA * BB * ODIM)
#define C_OFF (H_OFF + NROWS * HDIM)

// Scratch (fp16, natural k order)
__device__ __half g_xr[NROWS * IDIM];
__device__ __half g_win[16 * HDIM * IDIM];
__device__ __half g_wih[1536 * HDIM];      // packed row p = 3h+gate (f elided)
__device__ __half g_wout[16 * ODIM * HDIM];
__device__ __half g_xproj[NROWS * HDIM];   // relu projection
__device__ __half g_h1[NROWS * HDIM];      // h1
__device__ int    g_ord[AA];
__device__ int    g_sched[MAX_TILES][8];   // {species, a0..a3, pad}

__device__ __forceinline__ float sigmoidf_(float x) {
    return 1.0f / (1.0f + __expf(-x));
}

__device__ __forceinline__ void mma_f16(float* c, const unsigned* a, const unsigned* b) {
    asm volatile(
        "mma.sync.aligned.m16n8k16.row.col.f32.f16.f16.f32 "
        "{%0,%1,%2,%3}, {%4,%5,%6,%7}, {%8,%9}, {%0,%1,%2,%3};"
        : "+f"(c[0]), "+f"(c[1]), "+f"(c[2]), "+f"(c[3])
        : "r"(a[0]), "r"(a[1]), "r"(a[2]), "r"(a[3]), "r"(b[0]), "r"(b[1]));
}

__device__ __forceinline__ void ldsm_x4(unsigned* r, uint32_t addr) {
    asm volatile("ldmatrix.sync.aligned.m8n8.x4.shared.b16 {%0,%1,%2,%3}, [%4];"
                 : "=r"(r[0]), "=r"(r[1]), "=r"(r[2]), "=r"(r[3]) : "r"(addr));
}

__device__ __forceinline__ uint32_t s2u(const void* p) {
    uint32_t a;
    asm("{ .reg .u64 t; cvta.to.shared.u64 t, %1; cvt.u32.u64 %0, t; }" : "=r"(a) : "l"(p));
    return a;
}
__device__ __forceinline__ void cp16(uint32_t dst, const void* src) {
    asm volatile("cp.async.cg.shared.global [%0], [%1], 16;" :: "r"(dst), "l"(src));
}

// ---------------------------------------------------------------------------
// Schedule builder: species-bucketed 128-row tiles.
// ---------------------------------------------------------------------------
__global__ void k_build(const int* __restrict__ sp) {
    __shared__ int cnt[16], base[16], off[16], tb[17];
    int t = threadIdx.x;
    if (t < 16) cnt[t] = 0;
    __syncthreads();
    if (t < AA) atomicAdd(&cnt[sp[t]], 1);
    __syncthreads();
    if (t == 0) {
        int a = 0, tc = 0;
        for (int q = 0; q < 16; q++) {
            base[q] = a; off[q] = a; a += cnt[q];
            tb[q] = tc; tc += (cnt[q] + 3) >> 2;
        }
        tb[16] = tc;
    }
    __syncthreads();
    if (t < AA) {
        int s = sp[t];
        int slot = atomicAdd(&off[s], 1);
        g_ord[slot] = t;
    }
    __syncthreads();
    if (t < MAX_TILES) {
        int s = -1;
        for (int q = 0; q < 16; q++)
            if (t >= tb[q] && t < tb[q + 1]) s = q;
        g_sched[t][0] = s;
        if (s >= 0) {
            int ti = t - tb[s];
            #pragma unroll
            for (int j = 0; j < 4; j++) {
                int idx = ti * 4 + j;
                g_sched[t][1 + j] = (idx < cnt[s]) ? g_ord[base[s] + idx] : -1;
            }
        }
    }
}

// ---------------------------------------------------------------------------
// Convert x, w_in, w_out and interleave-pack w_ih to fp16 (natural order).
// ---------------------------------------------------------------------------
#define XR_E   (NROWS * IDIM)
#define WIN_E  (16 * HDIM * IDIM)
#define WOUT_E (16 * ODIM * HDIM)
#define WIH_E  (1536 * HDIM)
#define TOT_T  ((XR_E + WIN_E + WOUT_E + WIH_E) / 8)

__global__ void __launch_bounds__(256) k_cvt(
    const float4* __restrict__ x, const float4* __restrict__ w_in,
    const float* __restrict__ w_ih, const float4* __restrict__ w_out)
{
    int i = blockIdx.x * 256 + threadIdx.x;
    if (i >= TOT_T) return;
    float4 v0, v1; __half* dst; int e0;
    if (i < XR_E / 8) {
        e0 = i * 8; v0 = x[i*2]; v1 = x[i*2+1]; dst = g_xr;
    } else if (i < (XR_E + WIN_E) / 8) {
        int j = i - XR_E / 8; e0 = j * 8;
        v0 = w_in[j*2]; v1 = w_in[j*2+1]; dst = g_win;
    } else if (i < (XR_E + WIN_E + WOUT_E) / 8) {
        int j = i - (XR_E + WIN_E) / 8; e0 = j * 8;
        v0 = w_out[j*2]; v1 = w_out[j*2+1]; dst = g_wout;
    } else {
        int j = i - (XR_E + WIN_E + WOUT_E) / 8; e0 = j * 8;
        int p = e0 >> 9, c = e0 & 511;             // packed row p = 3h+gate
        int h = p / 3, gate = p - 3 * h;
        int sr = (gate == 0) ? h : (gate == 1) ? 1024 + h : 1536 + h;
        const float4* src = (const float4*)&w_ih[(size_t)sr * HDIM + c];
        v0 = src[0]; v1 = src[1]; dst = g_wih;
    }
    __half2 h2[4];
    h2[0] = __floats2half2_rn(v0.x, v0.y);
    h2[1] = __floats2half2_rn(v0.z, v0.w);
    h2[2] = __floats2half2_rn(v1.x, v1.y);
    h2[3] = __floats2half2_rn(v1.z, v1.w);
    *(uint4*)&dst[e0] = *(uint4*)h2;
}

// ---------------------------------------------------------------------------
// Pipelined fp16 m16n8k16 GEMM with ldmatrix fragment loads.
// SMEM rows: 144B stride (128B data + 16B pad) -> conflict-free LDSM.
// 3-stage cp.async ring, wait_group 1 before compute.
// 8 warps: warp grid 2(M) x 4(N).
// MODE 0: xproj  BN=128 (warp 64x32), 2 CTAs/SM, K=256: relu+bias -> g_xproj
// MODE 1: gates  BN=192 (warp 64x48), 1 CTA/SM,  K=512: interleaved i/g/o;
//                fused LSTM -> h_out/c_out (fp32) + h1 -> g_h1
// MODE 2: logits BN=128 (warp 64x32), 2 CTAs/SM, K=512: bias -> out (fp32)
// ---------------------------------------------------------------------------
#define ROWB 144

template <int MODE>
__global__ void __launch_bounds__(256, (MODE == 1) ? 1 : 2) k_gemm(
    const float* __restrict__ bias1, const float* __restrict__ bias2,
    float* __restrict__ Cout)
{
    constexpr int K = (MODE == 0) ? IDIM : HDIM;   // halves
    constexpr int NSLAB = K / 64;
    constexpr int BN = (MODE == 1) ? 192 : 128;
    constexpr int FN = (MODE == 1) ? 6 : 4;
    constexpr int NP = FN / 2;                     // B ldsm.x4 per kk
    constexpr int WN = FN * 8;                     // 48 / 32
    constexpr int ABYTES = 128 * ROWB;             // 18 KB
    constexpr int BBYTES = BN * ROWB;
    constexpr int STAGEB = ABYTES + BBYTES;

    extern __shared__ char smraw[];
    const uint32_t smbase = s2u(smraw);

    const int tid  = threadIdx.x;
    const int wid  = tid >> 5;
    const int lane = tid & 31;
    const int wm = wid >> 2;          // 0..1
    const int wn = wid & 3;           // 0..3
    const int lr = lane >> 2;         // 0..7
    const int lc = lane & 3;          // 0..3
    const int n0 = blockIdx.x * BN;

    int s = 0, m0 = 0;
    int aa[4] = {0, 0, 0, 0};
    int ab[4];
    const __half* Aptr;
    const __half* W;

    if (MODE == 1) {
        m0 = blockIdx.y * 128;
        ab[0] = m0; ab[1] = m0 + 32; ab[2] = m0 + 64; ab[3] = m0 + 96;
        Aptr = g_xproj;
        W = g_wih;
    } else {
        const int* t = g_sched[blockIdx.y];
        s = t[0];
        if (s < 0) return;
        int b0 = t[1];
        #pragma unroll
        for (int i = 0; i < 4; i++) {
            aa[i] = t[1 + i];
            ab[i] = ((aa[i] < 0) ? b0 : aa[i]) * 32;   // clamp pads (loads only)
        }
        Aptr = (MODE == 0) ? g_xr : g_h1;
        W = (MODE == 0) ? g_win + (size_t)s * HDIM * IDIM
                        : g_wout + (size_t)s * ODIM * HDIM;
    }

    auto load_slab = [&](int kt) {
        const int k0 = kt * 64;
        const uint32_t stb = smbase + (kt % 3) * STAGEB;
        #pragma unroll
        for (int i = 0; i < 4; i++) {              // A: 128 rows x 8 chunks
            int idx = tid + i * 256, r = idx >> 3, c = idx & 7;
            cp16(stb + r * ROWB + c * 16,
                 Aptr + (size_t)(ab[r >> 5] + (r & 31)) * K + k0 + c * 8);
        }
        #pragma unroll
        for (int i = 0; i < BN / 32; i++) {        // B: BN rows x 8 chunks
            int idx = tid + i * 256, r = idx >> 3, c = idx & 7;
            cp16(stb + ABYTES + r * ROWB + c * 16,
                 W + (size_t)(n0 + r) * K + k0 + c * 8);
        }
        asm volatile("cp.async.commit_group;");
    };

    // --- LDSM lane address offsets (linear; +32B per kk) ---
    const int aRow = (lane & 7) + ((lane >> 3) & 1) * 8;
    const int aK16 = (lane >> 4) * 16;
    uint32_t aoffL[4];
    #pragma unroll
    for (int fm = 0; fm < 4; fm++)
        aoffL[fm] = (uint32_t)((wm * 64 + fm * 16 + aRow) * ROWB + aK16);
    const int bRowP = (lane & 7) + ((lane >> 4) & 1) * 8;
    const int bK16  = ((lane >> 3) & 1) * 16;
    uint32_t boffP[NP];
    #pragma unroll
    for (int p = 0; p < NP; p++)
        boffP[p] = (uint32_t)(ABYTES + (wn * WN + p * 16 + bRowP) * ROWB + bK16);

    float acc[4][FN][4];
    #pragma unroll
    for (int a = 0; a < 4; a++)
        #pragma unroll
        for (int b = 0; b < FN; b++)
            #pragma unroll
            for (int c = 0; c < 4; c++) acc[a][b][c] = 0.0f;

    load_slab(0);
    load_slab(1);

    for (int kt = 0; kt < NSLAB; kt++) {
        if (kt + 1 < NSLAB) asm volatile("cp.async.wait_group 1;");
        else                asm volatile("cp.async.wait_group 0;");
        __syncthreads();                           // slab kt ready; kt-1 consumed
        if (kt + 2 < NSLAB) load_slab(kt + 2);     // into stage (kt-1)%3 (free)

        const uint32_t stb = smbase + (kt % 3) * STAGEB;

        #pragma unroll
        for (int kk = 0; kk < 4; kk++) {           // 16 k per kk
            const uint32_t kb = stb + kk * 32;
            unsigned af[4][4];
            #pragma unroll
            for (int fm = 0; fm < 4; fm++)
                ldsm_x4(af[fm], kb + aoffL[fm]);
            unsigned bf[FN][2];
            #pragma unroll
            for (int p = 0; p < NP; p++) {
                unsigned t4[4];
                ldsm_x4(t4, kb + boffP[p]);
                bf[2*p][0]   = t4[0]; bf[2*p][1]   = t4[1];
                bf[2*p+1][0] = t4[2]; bf[2*p+1][1] = t4[3];
            }
            #pragma unroll
            for (int fm = 0; fm < 4; fm++)
                #pragma unroll
                for (int fn = 0; fn < FN; fn++)
                    mma_f16(acc[fm][fn], af[fm], bf[fn]);
        }
    }

    // ------------------------------ Epilogue -------------------------------
    if (MODE == 1) {
        __syncthreads();                           // stages free for scratch
        float* scr = (float*)smraw + wid * (64 * 49);   // 64 rows x 48 cols pad 49
        #pragma unroll
        for (int fm = 0; fm < 4; fm++) {
            int rr0 = fm * 16 + lr;
            #pragma unroll
            for (int fn = 0; fn < FN; fn++) {
                int cc = fn * 8 + lc * 2;
                scr[rr0 * 49 + cc]            = acc[fm][fn][0];
                scr[rr0 * 49 + cc + 1]        = acc[fm][fn][1];
                scr[(rr0 + 8) * 49 + cc]      = acc[fm][fn][2];
                scr[(rr0 + 8) * 49 + cc + 1]  = acc[fm][fn][3];
            }
        }
        __syncwarp();
        const int hb = (n0 + wn * WN) / 3;         // 16 h per warp window
        const int rowb = m0 + wm * 64;
        #pragma unroll
        for (int it = 0; it < 32; it++) {
            int item = it * 32 + lane;             // 64 rows x 16 h
            int rr = item >> 4, hh = item & 15;
            int h = hb + hh;
            float gi = scr[rr * 49 + hh * 3    ] + bias1[h]        + bias2[h];
            float gg = scr[rr * 49 + hh * 3 + 1] + bias1[1024 + h] + bias2[1024 + h];
            float go = scr[rr * 49 + hh * 3 + 2] + bias1[1536 + h] + bias2[1536 + h];
            float c1 = sigmoidf_(gi) * tanhf(gg);  // f*c0 == 0
            float h1 = sigmoidf_(go) * tanhf(c1);
            size_t row = (size_t)(rowb + rr);
            Cout[H_OFF + row * HDIM + h] = h1;
            Cout[C_OFF + row * HDIM + h] = c1;
            g_h1[row * HDIM + h] = __float2half(h1);
        }
    } else {
        #pragma unroll
        for (int fm = 0; fm < 4; fm++) {
            int rl = wm * 64 + fm * 16 + lr;
            int grp = rl >> 5;
            if (aa[grp] < 0) continue;
            size_t grow0 = (size_t)aa[grp] * 32 + (rl & 31);
            size_t grow1 = grow0 + 8;
            #pragma unroll
            for (int fn = 0; fn < FN; fn++) {
                int col = n0 + wn * WN + fn * 8 + lc * 2;
                float v00 = acc[fm][fn][0], v01 = acc[fm][fn][1];
                float v10 = acc[fm][fn][2], v11 = acc[fm][fn][3];
                if (MODE == 0) {
                    float b0 = bias1[s * HDIM + col], b1 = bias1[s * HDIM + col + 1];
                    *(__half2*)&g_xproj[grow0 * HDIM + col] =
                        __floats2half2_rn(fmaxf(v00 + b0, 0.0f), fmaxf(v01 + b1, 0.0f));
                    *(__half2*)&g_xproj[grow1 * HDIM + col] =
                        __floats2half2_rn(fmaxf(v10 + b0, 0.0f), fmaxf(v11 + b1, 0.0f));
                } else {
                    float b0 = bias1[s * ODIM + col], b1 = bias1[s * ODIM + col + 1];
                    Cout[grow0 * ODIM + col    ] = v00 + b0;
                    Cout[grow0 * ODIM + col + 1] = v01 + b1;
                    Cout[grow1 * ODIM + col    ] = v10 + b0;
                    Cout[grow1 * ODIM + col + 1] = v11 + b1;
                }
            }
        }
    }
}

// ---------------------------------------------------------------------------
// inputs: 0 x, 1 species, 2 w_in, 3 b_in, 4 w_ih, 5 w_hh(unused), 6 b_ih,
//         7 b_hh, 8 w_out, 9 b_out
// ---------------------------------------------------------------------------
extern "C" void kernel_launch(void* const* d_in, const int* in_sizes, int n_in,
                              void* d_out, int out_size)
{
    const float* x     = (const float*)d_in[0];
    const int*   sp    = (const int*)d_in[1];
    const float* w_in  = (const float*)d_in[2];
    const float* b_in  = (const float*)d_in[3];
    const float* w_ih  = (const float*)d_in[4];
    const float* b_ih  = (const float*)d_in[6];
    const float* b_hh  = (const float*)d_in[7];
    const float* w_out = (const float*)d_in[8];
    const float* b_out = (const float*)d_in[9];
    float* out = (float*)d_out;

    const int SMEM02 = 3 * (128 * ROWB + 128 * ROWB);   // 108 KB
    const int SMEM1  = 3 * (128 * ROWB + 192 * ROWB);   // 135 KB

    static bool attr_done = false;
    if (!attr_done) {
        cudaFuncSetAttribute(k_gemm<0>, cudaFuncAttributeMaxDynamicSharedMemorySize, SMEM02);
        cudaFuncSetAttribute(k_gemm<1>, cudaFuncAttributeMaxDynamicSharedMemorySize, SMEM1);
        cudaFuncSetAttribute(k_gemm<2>, cudaFuncAttributeMaxDynamicSharedMemorySize, SMEM02);
        attr_done = true;
    }

    k_build<<<1, 512>>>(sp);

    k_cvt<<<(TOT_T + 255) / 256, 256>>>(
        (const float4*)x, (const float4*)w_in, w_ih, (const float4*)w_out);

    // xproj: N=512 -> 4 tiles of 128, species-scheduled M tiles
    k_gemm<0><<<dim3(4, MAX_TILES), 256, SMEM02>>>(b_in, nullptr, nullptr);

    // gates (interleaved 3h+gate, fused LSTM): N=1536 -> 8 tiles of 192
    k_gemm<1><<<dim3(8, NROWS / 128), 256, SMEM1>>>(b_ih, b_hh, out);

    // logits: N=1024 -> 8 tiles of 128, species-scheduled M tiles
    k_gemm<2><<<dim3(8, MAX_TILES), 256, SMEM02>>>(b_out, nullptr, out);
}

// round 16
// speedup vs baseline: 1.0959x; 1.0959x over previous
#include <cuda_runtime.h>
#include <cuda_fp16.h>
#include <math.h>
#include <stdint.h>

// Problem constants
#define AA 512
#define BB 32
#define IDIM 256
#define HDIM 512
#define ODIM 1024          // MSG_DIM * VOCAB
#define NROWS (AA * BB)    // 16384
#define MAX_TILES 160

// d_out layout: [logits] [h_out] [c_out]
#define LOGITS_OFF 0
#define H_OFF (AA * BB * ODIM)
#define C_OFF (H_OFF + NROWS * HDIM)

// Scratch (fp16, natural k order)
__device__ __half g_xr[NROWS * IDIM];
__device__ __half g_win[16 * HDIM * IDIM];
__device__ __half g_wih[1536 * HDIM];      // packed row p = 3h+gate (f elided)
__device__ __half g_wout[16 * ODIM * HDIM];
__device__ __half g_xproj[NROWS * HDIM];   // relu projection
__device__ __half g_h1[NROWS * HDIM];      // h1
__device__ int    g_ord[AA];
__device__ int    g_sched[MAX_TILES][8];   // {species, a0..a3, pad}

__device__ __forceinline__ float sigmoidf_(float x) {
    return 1.0f / (1.0f + __expf(-x));
}

__device__ __forceinline__ void mma_f16(float* c, const unsigned* a, const unsigned* b) {
    asm volatile(
        "mma.sync.aligned.m16n8k16.row.col.f32.f16.f16.f32 "
        "{%0,%1,%2,%3}, {%4,%5,%6,%7}, {%8,%9}, {%0,%1,%2,%3};"
        : "+f"(c[0]), "+f"(c[1]), "+f"(c[2]), "+f"(c[3])
        : "r"(a[0]), "r"(a[1]), "r"(a[2]), "r"(a[3]), "r"(b[0]), "r"(b[1]));
}

__device__ __forceinline__ void ldsm_x4(unsigned* r, uint32_t addr) {
    asm volatile("ldmatrix.sync.aligned.m8n8.x4.shared.b16 {%0,%1,%2,%3}, [%4];"
                 : "=r"(r[0]), "=r"(r[1]), "=r"(r[2]), "=r"(r[3]) : "r"(addr));
}
__device__ __forceinline__ void ldsm_x2(unsigned* r, uint32_t addr) {
    asm volatile("ldmatrix.sync.aligned.m8n8.x2.shared.b16 {%0,%1}, [%2];"
                 : "=r"(r[0]), "=r"(r[1]) : "r"(addr));
}

__device__ __forceinline__ uint32_t s2u(const void* p) {
    uint32_t a;
    asm("{ .reg .u64 t; cvta.to.shared.u64 t, %1; cvt.u32.u64 %0, t; }" : "=r"(a) : "l"(p));
    return a;
}
__device__ __forceinline__ void cp16(uint32_t dst, const void* src) {
    asm volatile("cp.async.cg.shared.global [%0], [%1], 16;" :: "r"(dst), "l"(src));
}

// ---------------------------------------------------------------------------
// Schedule builder: species-bucketed 128-row tiles.
// ---------------------------------------------------------------------------
__global__ void k_build(const int* __restrict__ sp) {
    __shared__ int cnt[16], base[16], off[16], tb[17];
    int t = threadIdx.x;
    if (t < 16) cnt[t] = 0;
    __syncthreads();
    if (t < AA) atomicAdd(&cnt[sp[t]], 1);
    __syncthreads();
    if (t == 0) {
        int a = 0, tc = 0;
        for (int q = 0; q < 16; q++) {
            base[q] = a; off[q] = a; a += cnt[q];
            tb[q] = tc; tc += (cnt[q] + 3) >> 2;
        }
        tb[16] = tc;
    }
    __syncthreads();
    if (t < AA) {
        int s = sp[t];
        int slot = atomicAdd(&off[s], 1);
        g_ord[slot] = t;
    }
    __syncthreads();
    if (t < MAX_TILES) {
        int s = -1;
        for (int q = 0; q < 16; q++)
            if (t >= tb[q] && t < tb[q + 1]) s = q;
        g_sched[t][0] = s;
        if (s >= 0) {
            int ti = t - tb[s];
            #pragma unroll
            for (int j = 0; j < 4; j++) {
                int idx = ti * 4 + j;
                g_sched[t][1 + j] = (idx < cnt[s]) ? g_ord[base[s] + idx] : -1;
            }
        }
    }
}

// ---------------------------------------------------------------------------
// Convert x, w_in, w_out and interleave-pack w_ih to fp16 (natural order).
// ---------------------------------------------------------------------------
#define XR_E   (NROWS * IDIM)
#define WIN_E  (16 * HDIM * IDIM)
#define WOUT_E (16 * ODIM * HDIM)
#define WIH_E  (1536 * HDIM)
#define TOT_T  ((XR_E + WIN_E + WOUT_E + WIH_E) / 8)

__global__ void __launch_bounds__(256) k_cvt(
    const float4* __restrict__ x, const float4* __restrict__ w_in,
    const float* __restrict__ w_ih, const float4* __restrict__ w_out)
{
    int i = blockIdx.x * 256 + threadIdx.x;
    if (i >= TOT_T) return;
    float4 v0, v1; __half* dst; int e0;
    if (i < XR_E / 8) {
        e0 = i * 8; v0 = x[i*2]; v1 = x[i*2+1]; dst = g_xr;
    } else if (i < (XR_E + WIN_E) / 8) {
        int j = i - XR_E / 8; e0 = j * 8;
        v0 = w_in[j*2]; v1 = w_in[j*2+1]; dst = g_win;
    } else if (i < (XR_E + WIN_E + WOUT_E) / 8) {
        int j = i - (XR_E + WIN_E) / 8; e0 = j * 8;
        v0 = w_out[j*2]; v1 = w_out[j*2+1]; dst = g_wout;
    } else {
        int j = i - (XR_E + WIN_E + WOUT_E) / 8; e0 = j * 8;
        int p = e0 >> 9, c = e0 & 511;             // packed row p = 3h+gate
        int h = p / 3, gate = p - 3 * h;
        int sr = (gate == 0) ? h : (gate == 1) ? 1024 + h : 1536 + h;
        const float4* src = (const float4*)&w_ih[(size_t)sr * HDIM + c];
        v0 = src[0]; v1 = src[1]; dst = g_wih;
    }
    __half2 h2[4];
    h2[0] = __floats2half2_rn(v0.x, v0.y);
    h2[1] = __floats2half2_rn(v0.z, v0.w);
    h2[2] = __floats2half2_rn(v1.x, v1.y);
    h2[3] = __floats2half2_rn(v1.z, v1.w);
    *(uint4*)&dst[e0] = *(uint4*)h2;
}

// ---------------------------------------------------------------------------
// Pipelined fp16 m16n8k16 GEMM with ldmatrix fragment loads.
// SMEM rows: 144B stride (128B data + 16B pad) -> conflict-free LDSM.
// 8 warps: warp grid 2(M) x 4(N), warp tile 64xWN. 2 CTAs/SM.
// STAGES: gates uses a 3-stage ring w/ wait_group 1 (best measured, R13);
//         modes 0/2 use the 2-stage ring (best measured, R11).
// MODE 0: xproj  BN=128 (warp 64x32), K=256: relu+bias -> g_xproj
// MODE 1: gates  BN=96  (warp 64x24), K=512: interleaved i/g/o; fused LSTM ->
//                h_out/c_out (fp32) + h1 -> g_h1
// MODE 2: logits BN=128 (warp 64x32), K=512: bias -> out (fp32)
// ---------------------------------------------------------------------------
#define ROWB 144

template <int MODE>
__global__ void __launch_bounds__(256, 2) k_gemm(
    const float* __restrict__ bias1, const float* __restrict__ bias2,
    float* __restrict__ Cout)
{
    constexpr int K = (MODE == 0) ? IDIM : HDIM;   // halves
    constexpr int NSLAB = K / 64;
    constexpr int BN = (MODE == 1) ? 96 : 128;
    constexpr int FN = (MODE == 1) ? 3 : 4;
    constexpr int WN = FN * 8;
    constexpr int STAGES = (MODE == 1) ? 3 : 2;
    constexpr int ABYTES = 128 * ROWB;             // 18 KB
    constexpr int BBYTES = BN * ROWB;
    constexpr int STAGEB = ABYTES + BBYTES;

    extern __shared__ char smraw[];
    const uint32_t smbase = s2u(smraw);

    const int tid  = threadIdx.x;
    const int wid  = tid >> 5;
    const int lane = tid & 31;
    const int wm = wid >> 2;          // 0..1
    const int wn = wid & 3;           // 0..3
    const int lr = lane >> 2;         // 0..7
    const int lc = lane & 3;          // 0..3
    const int n0 = blockIdx.x * BN;

    int s = 0, m0 = 0;
    int aa[4] = {0, 0, 0, 0};
    int ab[4];
    const __half* Aptr;
    const __half* W;

    if (MODE == 1) {
        m0 = blockIdx.y * 128;
        ab[0] = m0; ab[1] = m0 + 32; ab[2] = m0 + 64; ab[3] = m0 + 96;
        Aptr = g_xproj;
        W = g_wih;
    } else {
        const int* t = g_sched[blockIdx.y];
        s = t[0];
        if (s < 0) return;
        int b0 = t[1];
        #pragma unroll
        for (int i = 0; i < 4; i++) {
            aa[i] = t[1 + i];
            ab[i] = ((aa[i] < 0) ? b0 : aa[i]) * 32;   // clamp pads (loads only)
        }
        Aptr = (MODE == 0) ? g_xr : g_h1;
        W = (MODE == 0) ? g_win + (size_t)s * HDIM * IDIM
                        : g_wout + (size_t)s * ODIM * HDIM;
    }

    auto load_slab = [&](int kt) {
        const int k0 = kt * 64;
        const uint32_t stb = smbase + (kt % STAGES) * STAGEB;
        #pragma unroll
        for (int i = 0; i < 4; i++) {              // A: 128 rows x 8 chunks
            int idx = tid + i * 256, r = idx >> 3, c = idx & 7;
            cp16(stb + r * ROWB + c * 16,
                 Aptr + (size_t)(ab[r >> 5] + (r & 31)) * K + k0 + c * 8);
        }
        #pragma unroll
        for (int i = 0; i < BN / 32; i++) {        // B: BN rows x 8 chunks
            int idx = tid + i * 256, r = idx >> 3, c = idx & 7;
            cp16(stb + ABYTES + r * ROWB + c * 16,
                 W + (size_t)(n0 + r) * K + k0 + c * 8);
        }
        asm volatile("cp.async.commit_group;");
    };

    // --- LDSM lane address offsets (linear; +32B per kk) ---
    const int aRow = (lane & 7) + ((lane >> 3) & 1) * 8;
    const int aK16 = (lane >> 4) * 16;
    uint32_t aoffL[4];
    #pragma unroll
    for (int fm = 0; fm < 4; fm++)
        aoffL[fm] = (uint32_t)((wm * 64 + fm * 16 + aRow) * ROWB + aK16);
    const int bRowP = (lane & 7) + ((lane >> 4) & 1) * 8;
    const int bK16  = ((lane >> 3) & 1) * 16;
    uint32_t boffP0 = (uint32_t)(ABYTES + (wn * WN + bRowP) * ROWB + bK16);
    uint32_t boffP1 = boffP0 + 16 * ROWB;          // fns 2,3 (FN==4)
    uint32_t boff2  = (uint32_t)(ABYTES + (wn * WN + 16 + (lane & 7)) * ROWB + bK16);

    float acc[4][FN][4];
    #pragma unroll
    for (int a = 0; a < 4; a++)
        #pragma unroll
        for (int b = 0; b < FN; b++)
            #pragma unroll
            for (int c = 0; c < 4; c++) acc[a][b][c] = 0.0f;

    load_slab(0);
    if (STAGES == 3) load_slab(1);

    for (int kt = 0; kt < NSLAB; kt++) {
        if (STAGES == 3) {
            if (kt + 1 < NSLAB) asm volatile("cp.async.wait_group 1;");
            else                asm volatile("cp.async.wait_group 0;");
            __syncthreads();                       // slab kt ready; kt-1 consumed
            if (kt + 2 < NSLAB) load_slab(kt + 2); // into stage (kt-1)%3 (free)
        } else {
            asm volatile("cp.async.wait_group 0;");
            __syncthreads();                       // data ready; prev compute done
            if (kt + 1 < NSLAB) load_slab(kt + 1); // overlaps with compute below
        }

        const uint32_t stb = smbase + (kt % STAGES) * STAGEB;

        #pragma unroll
        for (int kk = 0; kk < 4; kk++) {           // 16 k per kk
            const uint32_t kb = stb + kk * 32;
            unsigned af[4][4];
            #pragma unroll
            for (int fm = 0; fm < 4; fm++)
                ldsm_x4(af[fm], kb + aoffL[fm]);
            unsigned bf[FN][2];
            if (FN == 3) {
                unsigned t4[4];
                ldsm_x4(t4, kb + boffP0);
                bf[0][0] = t4[0]; bf[0][1] = t4[1];
                bf[1][0] = t4[2]; bf[1][1] = t4[3];
                ldsm_x2(bf[2], kb + boff2);
            } else {
                unsigned t4[4];
                ldsm_x4(t4, kb + boffP0);
                bf[0][0] = t4[0]; bf[0][1] = t4[1];
                bf[1][0] = t4[2]; bf[1][1] = t4[3];
                unsigned u4[4];
                ldsm_x4(u4, kb + boffP1);
                bf[2][0] = u4[0]; bf[2][1] = u4[1];
                bf[3][0] = u4[2]; bf[3][1] = u4[3];
            }
            #pragma unroll
            for (int fm = 0; fm < 4; fm++)
                #pragma unroll
                for (int fn = 0; fn < FN; fn++)
                    mma_f16(acc[fm][fn], af[fm], bf[fn]);
        }
        if (STAGES == 2) __syncthreads();          // protect stage before reload
    }

    // ------------------------------ Epilogue -------------------------------
    if (MODE == 1) {
        __syncthreads();                           // stages free for scratch
        float* scr = (float*)smraw + wid * (64 * 25);   // 64 rows x 24 cols pad 25
        #pragma unroll
        for (int fm = 0; fm < 4; fm++) {
            int rr0 = fm * 16 + lr;
            #pragma unroll
            for (int fn = 0; fn < FN; fn++) {
                int cc = fn * 8 + lc * 2;
                scr[rr0 * 25 + cc]            = acc[fm][fn][0];
                scr[rr0 * 25 + cc + 1]        = acc[fm][fn][1];
                scr[(rr0 + 8) * 25 + cc]      = acc[fm][fn][2];
                scr[(rr0 + 8) * 25 + cc + 1]  = acc[fm][fn][3];
            }
        }
        __syncwarp();
        const int hb = (n0 + wn * WN) / 3;         // 8 h per warp window
        const int rowb = m0 + wm * 64;
        #pragma unroll
        for (int it = 0; it < 16; it++) {
            int item = it * 32 + lane;             // 64 rows x 8 h
            int rr = item >> 3, hh = item & 7;
            int h = hb + hh;
            float gi = scr[rr * 25 + hh * 3    ] + bias1[h]        + bias2[h];
            float gg = scr[rr * 25 + hh * 3 + 1] + bias1[1024 + h] + bias2[1024 + h];
            float go = scr[rr * 25 + hh * 3 + 2] + bias1[1536 + h] + bias2[1536 + h];
            float c1 = sigmoidf_(gi) * tanhf(gg);  // f*c0 == 0
            float h1 = sigmoidf_(go) * tanhf(c1);
            size_t row = (size_t)(rowb + rr);
            Cout[H_OFF + row * HDIM + h] = h1;
            Cout[C_OFF + row * HDIM + h] = c1;
            g_h1[row * HDIM + h] = __float2half(h1);
        }
    } else {
        #pragma unroll
        for (int fm = 0; fm < 4; fm++) {
            int rl = wm * 64 + fm * 16 + lr;
            int grp = rl >> 5;
            if (aa[grp] < 0) continue;
            size_t grow0 = (size_t)aa[grp] * 32 + (rl & 31);
            size_t grow1 = grow0 + 8;
            #pragma unroll
            for (int fn = 0; fn < FN; fn++) {
                int col = n0 + wn * WN + fn * 8 + lc * 2;
                float v00 = acc[fm][fn][0], v01 = acc[fm][fn][1];
                float v10 = acc[fm][fn][2], v11 = acc[fm][fn][3];
                if (MODE == 0) {
                    float b0 = bias1[s * HDIM + col], b1 = bias1[s * HDIM + col + 1];
                    *(__half2*)&g_xproj[grow0 * HDIM + col] =
                        __floats2half2_rn(fmaxf(v00 + b0, 0.0f), fmaxf(v01 + b1, 0.0f));
                    *(__half2*)&g_xproj[grow1 * HDIM + col] =
                        __floats2half2_rn(fmaxf(v10 + b0, 0.0f), fmaxf(v11 + b1, 0.0f));
                } else {
                    float b0 = bias1[s * ODIM + col], b1 = bias1[s * ODIM + col + 1];
                    Cout[grow0 * ODIM + col    ] = v00 + b0;
                    Cout[grow0 * ODIM + col + 1] = v01 + b1;
                    Cout[grow1 * ODIM + col    ] = v10 + b0;
                    Cout[grow1 * ODIM + col + 1] = v11 + b1;
                }
            }
        }
    }
}

// ---------------------------------------------------------------------------
// inputs: 0 x, 1 species, 2 w_in, 3 b_in, 4 w_ih, 5 w_hh(unused), 6 b_ih,
//         7 b_hh, 8 w_out, 9 b_out
// ---------------------------------------------------------------------------
extern "C" void kernel_launch(void* const* d_in, const int* in_sizes, int n_in,
                              void* d_out, int out_size)
{
    const float* x     = (const float*)d_in[0];
    const int*   sp    = (const int*)d_in[1];
    const float* w_in  = (const float*)d_in[2];
    const float* b_in  = (const float*)d_in[3];
    const float* w_ih  = (const float*)d_in[4];
    const float* b_ih  = (const float*)d_in[6];
    const float* b_hh  = (const float*)d_in[7];
    const float* w_out = (const float*)d_in[8];
    const float* b_out = (const float*)d_in[9];
    float* out = (float*)d_out;

    const int SMEM02 = 2 * (128 * ROWB + 128 * ROWB);   // 72 KB (2-stage)
    const int SMEM1  = 3 * (128 * ROWB + 96 * ROWB);    // 94.5 KB (3-stage)

    static bool attr_done = false;
    if (!attr_done) {
        cudaFuncSetAttribute(k_gemm<0>, cudaFuncAttributeMaxDynamicSharedMemorySize, SMEM02);
        cudaFuncSetAttribute(k_gemm<1>, cudaFuncAttributeMaxDynamicSharedMemorySize, SMEM1);
        cudaFuncSetAttribute(k_gemm<2>, cudaFuncAttributeMaxDynamicSharedMemorySize, SMEM02);
        attr_done = true;
    }

    k_build<<<1, 512>>>(sp);

    k_cvt<<<(TOT_T + 255) / 256, 256>>>(
        (const float4*)x, (const float4*)w_in, w_ih, (const float4*)w_out);

    // xproj: N=512 -> 4 tiles of 128, species-scheduled M tiles
    k_gemm<0><<<dim3(4, MAX_TILES), 256, SMEM02>>>(b_in, nullptr, nullptr);

    // gates (interleaved 3h+gate, fused LSTM): N=1536 -> 16 tiles of 96
    k_gemm<1><<<dim3(16, NROWS / 128), 256, SMEM1>>>(b_ih, b_hh, out);

    // logits: N=1024 -> 8 tiles of 128, species-scheduled M tiles
    k_gemm<2><<<dim3(8, MAX_TILES), 256, SMEM02>>>(b_out, nullptr, out);
}

// round 17
// speedup vs baseline: 1.1285x; 1.0298x over previous
#include <cuda_runtime.h>
#include <cuda_fp16.h>
#include <math.h>
#include <stdint.h>

// Problem constants
#define AA 512
#define BB 32
#define IDIM 256
#define HDIM 512
#define ODIM 1024          // MSG_DIM * VOCAB
#define NROWS (AA * BB)    // 16384
#define MAX_TILES 160

// d_out layout: [logits] [h_out] [c_out]
#define LOGITS_OFF 0
#define H_OFF (AA * BB * ODIM)
#define C_OFF (H_OFF + NROWS * HDIM)

// Scratch (fp16, natural k order)
__device__ __half g_xr[NROWS * IDIM];
__device__ __half g_win[16 * HDIM * IDIM];
__device__ __half g_wih[1536 * HDIM];      // packed row p = 3h+gate (f elided)
__device__ __half g_wout[16 * ODIM * HDIM];
__device__ __half g_xproj[NROWS * HDIM];   // relu projection
__device__ __half g_h1[NROWS * HDIM];      // h1
__device__ int    g_ord[AA];
__device__ int    g_sched[MAX_TILES][8];   // {species, a0..a3, pad}

__device__ __forceinline__ float sigmoidf_(float x) {
    return 1.0f / (1.0f + __expf(-x));
}

__device__ __forceinline__ void mma_f16(float* c, const unsigned* a, const unsigned* b) {
    asm volatile(
        "mma.sync.aligned.m16n8k16.row.col.f32.f16.f16.f32 "
        "{%0,%1,%2,%3}, {%4,%5,%6,%7}, {%8,%9}, {%0,%1,%2,%3};"
        : "+f"(c[0]), "+f"(c[1]), "+f"(c[2]), "+f"(c[3])
        : "r"(a[0]), "r"(a[1]), "r"(a[2]), "r"(a[3]), "r"(b[0]), "r"(b[1]));
}

__device__ __forceinline__ void ldsm_x4(unsigned* r, uint32_t addr) {
    asm volatile("ldmatrix.sync.aligned.m8n8.x4.shared.b16 {%0,%1,%2,%3}, [%4];"
                 : "=r"(r[0]), "=r"(r[1]), "=r"(r[2]), "=r"(r[3]) : "r"(addr));
}
__device__ __forceinline__ void ldsm_x2(unsigned* r, uint32_t addr) {
    asm volatile("ldmatrix.sync.aligned.m8n8.x2.shared.b16 {%0,%1}, [%2];"
                 : "=r"(r[0]), "=r"(r[1]) : "r"(addr));
}

__device__ __forceinline__ uint32_t s2u(const void* p) {
    uint32_t a;
    asm("{ .reg .u64 t; cvta.to.shared.u64 t, %1; cvt.u32.u64 %0, t; }" : "=r"(a) : "l"(p));
    return a;
}
__device__ __forceinline__ void cp16(uint32_t dst, const void* src) {
    asm volatile("cp.async.cg.shared.global [%0], [%1], 16;" :: "r"(dst), "l"(src));
}

// ---------------------------------------------------------------------------
// Prep kernel: blocks [0, NBLK) convert inputs to fp16; block NBLK builds the
// species-bucketed schedule (256-thread version of k_build).
// ---------------------------------------------------------------------------
#define XR_E   (NROWS * IDIM)
#define WIN_E  (16 * HDIM * IDIM)
#define WOUT_E (16 * ODIM * HDIM)
#define WIH_E  (1536 * HDIM)
#define TOT_T  ((XR_E + WIN_E + WOUT_E + WIH_E) / 8)
#define NBLK   (TOT_T / 256)               // 1933312/256 = 7552 exact

__global__ void __launch_bounds__(256) k_prep(
    const float4* __restrict__ x, const float4* __restrict__ w_in,
    const float* __restrict__ w_ih, const float4* __restrict__ w_out,
    const int* __restrict__ sp)
{
    __shared__ int cnt[16], base[16], off[16], tb[17];
    if (blockIdx.x == NBLK) {
        int t = threadIdx.x;
        if (t < 16) cnt[t] = 0;
        __syncthreads();
        atomicAdd(&cnt[sp[t]], 1);
        atomicAdd(&cnt[sp[t + 256]], 1);
        __syncthreads();
        if (t == 0) {
            int a = 0, tc = 0;
            for (int q = 0; q < 16; q++) {
                base[q] = a; off[q] = a; a += cnt[q];
                tb[q] = tc; tc += (cnt[q] + 3) >> 2;
            }
            tb[16] = tc;
        }
        __syncthreads();
        {
            int s0 = sp[t];
            g_ord[atomicAdd(&off[s0], 1)] = t;
            int s1 = sp[t + 256];
            g_ord[atomicAdd(&off[s1], 1)] = t + 256;
        }
        __syncthreads();
        if (t < MAX_TILES) {
            int s = -1;
            for (int q = 0; q < 16; q++)
                if (t >= tb[q] && t < tb[q + 1]) s = q;
            g_sched[t][0] = s;
            if (s >= 0) {
                int ti = t - tb[s];
                #pragma unroll
                for (int j = 0; j < 4; j++) {
                    int idx = ti * 4 + j;
                    g_sched[t][1 + j] = (idx < cnt[s]) ? g_ord[base[s] + idx] : -1;
                }
            }
        }
        return;
    }

    int i = blockIdx.x * 256 + threadIdx.x;
    float4 v0, v1; __half* dst; int e0;
    if (i < XR_E / 8) {
        e0 = i * 8; v0 = x[i*2]; v1 = x[i*2+1]; dst = g_xr;
    } else if (i < (XR_E + WIN_E) / 8) {
        int j = i - XR_E / 8; e0 = j * 8;
        v0 = w_in[j*2]; v1 = w_in[j*2+1]; dst = g_win;
    } else if (i < (XR_E + WIN_E + WOUT_E) / 8) {
        int j = i - (XR_E + WIN_E) / 8; e0 = j * 8;
        v0 = w_out[j*2]; v1 = w_out[j*2+1]; dst = g_wout;
    } else {
        int j = i - (XR_E + WIN_E + WOUT_E) / 8; e0 = j * 8;
        int p = e0 >> 9, c = e0 & 511;             // packed row p = 3h+gate
        int h = p / 3, gate = p - 3 * h;
        int sr = (gate == 0) ? h : (gate == 1) ? 1024 + h : 1536 + h;
        const float4* src = (const float4*)&w_ih[(size_t)sr * HDIM + c];
        v0 = src[0]; v1 = src[1]; dst = g_wih;
    }
    __half2 h2[4];
    h2[0] = __floats2half2_rn(v0.x, v0.y);
    h2[1] = __floats2half2_rn(v0.z, v0.w);
    h2[2] = __floats2half2_rn(v1.x, v1.y);
    h2[3] = __floats2half2_rn(v1.z, v1.w);
    *(uint4*)&dst[e0] = *(uint4*)h2;
}

// ---------------------------------------------------------------------------
// Pipelined fp16 m16n8k16 GEMM, ldmatrix fragments, 144B smem rows.
// 128-thread CTAs (4 warps, warp grid 1M x 4N), BM=64, 4 CTAs/SM:
// same 16 warps/SM as before but barriers span only 4 warps and the 4
// independent CTAs drift out of phase (desynchronized LDSM/MMA bursts).
// 2-stage cp.async ring.
// MODE 0: xproj  BN=128 (warp 64x32), K=256: relu+bias -> g_xproj
// MODE 1: gates  BN=96  (warp 64x24), K=512: interleaved i/g/o; fused LSTM ->
//                h_out/c_out (fp32) + h1 -> g_h1
// MODE 2: logits BN=128 (warp 64x32), K=512: bias -> out (fp32)
// ---------------------------------------------------------------------------
#define ROWB 144

template <int MODE>
__global__ void __launch_bounds__(128, 4) k_gemm(
    const float* __restrict__ bias1, const float* __restrict__ bias2,
    float* __restrict__ Cout)
{
    constexpr int K = (MODE == 0) ? IDIM : HDIM;   // halves
    constexpr int NSLAB = K / 64;
    constexpr int BN = (MODE == 1) ? 96 : 128;
    constexpr int FN = (MODE == 1) ? 3 : 4;
    constexpr int WN = FN * 8;
    constexpr int ABYTES = 64 * ROWB;              // 9 KB
    constexpr int BBYTES = BN * ROWB;
    constexpr int STAGEB = ABYTES + BBYTES;

    extern __shared__ char smraw[];
    const uint32_t smbase = s2u(smraw);

    const int tid  = threadIdx.x;                  // 0..127
    const int wn   = tid >> 5;                     // 0..3 (N window)
    const int lane = tid & 31;
    const int lr = lane >> 2;                      // 0..7
    const int lc = lane & 3;                       // 0..3
    const int n0 = blockIdx.x * BN;

    int s = 0, m0 = 0;
    int aa[2] = {0, 0};
    int ab[2];
    const __half* Aptr;
    const __half* W;

    if (MODE == 1) {
        m0 = blockIdx.y * 64;
        ab[0] = m0; ab[1] = m0 + 32;
        Aptr = g_xproj;
        W = g_wih;
    } else {
        const int* t = g_sched[blockIdx.y >> 1];
        s = t[0];
        if (s < 0) return;
        int sub = blockIdx.y & 1;
        aa[0] = t[1 + 2 * sub];
        aa[1] = t[2 + 2 * sub];
        if (aa[0] < 0) return;                     // whole subtile is padding
        ab[0] = aa[0] * 32;
        ab[1] = ((aa[1] < 0) ? aa[0] : aa[1]) * 32;   // clamp pad (loads only)
        Aptr = (MODE == 0) ? g_xr : g_h1;
        W = (MODE == 0) ? g_win + (size_t)s * HDIM * IDIM
                        : g_wout + (size_t)s * ODIM * HDIM;
    }

    auto load_slab = [&](int kt) {
        const int k0 = kt * 64;
        const uint32_t stb = smbase + (kt & 1) * STAGEB;
        #pragma unroll
        for (int i = 0; i < 4; i++) {              // A: 64 rows x 8 chunks
            int idx = tid + i * 128, r = idx >> 3, c = idx & 7;
            cp16(stb + r * ROWB + c * 16,
                 Aptr + (size_t)(ab[r >> 5] + (r & 31)) * K + k0 + c * 8);
        }
        #pragma unroll
        for (int i = 0; i < BN / 16; i++) {        // B: BN rows x 8 chunks
            int idx = tid + i * 128, r = idx >> 3, c = idx & 7;
            cp16(stb + ABYTES + r * ROWB + c * 16,
                 W + (size_t)(n0 + r) * K + k0 + c * 8);
        }
        asm volatile("cp.async.commit_group;");
    };

    // --- LDSM lane address offsets (linear; +32B per kk) ---
    const int aRow = (lane & 7) + ((lane >> 3) & 1) * 8;
    const int aK16 = (lane >> 4) * 16;
    uint32_t aoffL[4];
    #pragma unroll
    for (int fm = 0; fm < 4; fm++)
        aoffL[fm] = (uint32_t)((fm * 16 + aRow) * ROWB + aK16);
    const int bRowP = (lane & 7) + ((lane >> 4) & 1) * 8;
    const int bK16  = ((lane >> 3) & 1) * 16;
    uint32_t boffP0 = (uint32_t)(ABYTES + (wn * WN + bRowP) * ROWB + bK16);
    uint32_t boffP1 = boffP0 + 16 * ROWB;          // fns 2,3 (FN==4)
    uint32_t boff2  = (uint32_t)(ABYTES + (wn * WN + 16 + (lane & 7)) * ROWB + bK16);

    float acc[4][FN][4];
    #pragma unroll
    for (int a = 0; a < 4; a++)
        #pragma unroll
        for (int b = 0; b < FN; b++)
            #pragma unroll
            for (int c = 0; c < 4; c++) acc[a][b][c] = 0.0f;

    load_slab(0);

    for (int kt = 0; kt < NSLAB; kt++) {
        asm volatile("cp.async.wait_group 0;");
        __syncthreads();                           // data ready; prev compute done
        if (kt + 1 < NSLAB) load_slab(kt + 1);     // overlaps with compute below

        const uint32_t stb = smbase + (kt & 1) * STAGEB;

        #pragma unroll
        for (int kk = 0; kk < 4; kk++) {           // 16 k per kk
            const uint32_t kb = stb + kk * 32;
            unsigned af[4][4];
            #pragma unroll
            for (int fm = 0; fm < 4; fm++)
                ldsm_x4(af[fm], kb + aoffL[fm]);
            unsigned bf[FN][2];
            if (FN == 3) {
                unsigned t4[4];
                ldsm_x4(t4, kb + boffP0);
                bf[0][0] = t4[0]; bf[0][1] = t4[1];
                bf[1][0] = t4[2]; bf[1][1] = t4[3];
                ldsm_x2(bf[2], kb + boff2);
            } else {
                unsigned t4[4];
                ldsm_x4(t4, kb + boffP0);
                bf[0][0] = t4[0]; bf[0][1] = t4[1];
                bf[1][0] = t4[2]; bf[1][1] = t4[3];
                unsigned u4[4];
                ldsm_x4(u4, kb + boffP1);
                bf[2][0] = u4[0]; bf[2][1] = u4[1];
                bf[3][0] = u4[2]; bf[3][1] = u4[3];
            }
            #pragma unroll
            for (int fm = 0; fm < 4; fm++)
                #pragma unroll
                for (int fn = 0; fn < FN; fn++)
                    mma_f16(acc[fm][fn], af[fm], bf[fn]);
        }
    }

    // ------------------------------ Epilogue -------------------------------
    if (MODE == 1) {
        __syncthreads();                           // stages free for scratch
        float* scr = (float*)smraw + wn * (64 * 25);    // 64 rows x 24 cols pad 25
        #pragma unroll
        for (int fm = 0; fm < 4; fm++) {
            int rr0 = fm * 16 + lr;
            #pragma unroll
            for (int fn = 0; fn < FN; fn++) {
                int cc = fn * 8 + lc * 2;
                scr[rr0 * 25 + cc]            = acc[fm][fn][0];
                scr[rr0 * 25 + cc + 1]        = acc[fm][fn][1];
                scr[(rr0 + 8) * 25 + cc]      = acc[fm][fn][2];
                scr[(rr0 + 8) * 25 + cc + 1]  = acc[fm][fn][3];
            }
        }
        __syncwarp();
        const int hb = (n0 + wn * WN) / 3;         // 8 h per warp window
        #pragma unroll
        for (int it = 0; it < 16; it++) {
            int item = it * 32 + lane;             // 64 rows x 8 h
            int rr = item >> 3, hh = item & 7;
            int h = hb + hh;
            float gi = scr[rr * 25 + hh * 3    ] + bias1[h]        + bias2[h];
            float gg = scr[rr * 25 + hh * 3 + 1] + bias1[1024 + h] + bias2[1024 + h];
            float go = scr[rr * 25 + hh * 3 + 2] + bias1[1536 + h] + bias2[1536 + h];
            float c1 = sigmoidf_(gi) * tanhf(gg);  // f*c0 == 0
            float h1 = sigmoidf_(go) * tanhf(c1);
            size_t row = (size_t)(m0 + rr);
            Cout[H_OFF + row * HDIM + h] = h1;
            Cout[C_OFF + row * HDIM + h] = c1;
            g_h1[row * HDIM + h] = __float2half(h1);
        }
    } else {
        #pragma unroll
        for (int fm = 0; fm < 4; fm++) {
            int rl = fm * 16 + lr;                 // 0..63
            int grp = rl >> 5;
            if (aa[grp] < 0) continue;
            size_t grow0 = (size_t)aa[grp] * 32 + (rl & 31);
            size_t grow1 = grow0 + 8;
            #pragma unroll
            for (int fn = 0; fn < FN; fn++) {
                int col = n0 + wn * WN + fn * 8 + lc * 2;
                float v00 = acc[fm][fn][0], v01 = acc[fm][fn][1];
                float v10 = acc[fm][fn][2], v11 = acc[fm][fn][3];
                if (MODE == 0) {
                    float b0 = bias1[s * HDIM + col], b1 = bias1[s * HDIM + col + 1];
                    *(__half2*)&g_xproj[grow0 * HDIM + col] =
                        __floats2half2_rn(fmaxf(v00 + b0, 0.0f), fmaxf(v01 + b1, 0.0f));
                    *(__half2*)&g_xproj[grow1 * HDIM + col] =
                        __floats2half2_rn(fmaxf(v10 + b0, 0.0f), fmaxf(v11 + b1, 0.0f));
                } else {
                    float b0 = bias1[s * ODIM + col], b1 = bias1[s * ODIM + col + 1];
                    Cout[grow0 * ODIM + col    ] = v00 + b0;
                    Cout[grow0 * ODIM + col + 1] = v01 + b1;
                    Cout[grow1 * ODIM + col    ] = v10 + b0;
                    Cout[grow1 * ODIM + col + 1] = v11 + b1;
                }
            }
        }
    }
}

// ---------------------------------------------------------------------------
// inputs: 0 x, 1 species, 2 w_in, 3 b_in, 4 w_ih, 5 w_hh(unused), 6 b_ih,
//         7 b_hh, 8 w_out, 9 b_out
// ---------------------------------------------------------------------------
extern "C" void kernel_launch(void* const* d_in, const int* in_sizes, int n_in,
                              void* d_out, int out_size)
{
    const float* x     = (const float*)d_in[0];
    const int*   sp    = (const int*)d_in[1];
    const float* w_in  = (const float*)d_in[2];
    const float* b_in  = (const float*)d_in[3];
    const float* w_ih  = (const float*)d_in[4];
    const float* b_ih  = (const float*)d_in[6];
    const float* b_hh  = (const float*)d_in[7];
    const float* w_out = (const float*)d_in[8];
    const float* b_out = (const float*)d_in[9];
    float* out = (float*)d_out;

    const int SMEM02 = 2 * (64 * ROWB + 128 * ROWB);   // 55.3 KB (4 CTAs/SM)
    const int SMEM1  = 2 * (64 * ROWB + 96 * ROWB);    // 46 KB   (4 CTAs/SM)

    static bool attr_done = false;
    if (!attr_done) {
        cudaFuncSetAttribute(k_gemm<0>, cudaFuncAttributeMaxDynamicSharedMemorySize, SMEM02);
        cudaFuncSetAttribute(k_gemm<1>, cudaFuncAttributeMaxDynamicSharedMemorySize, SMEM1);
        cudaFuncSetAttribute(k_gemm<2>, cudaFuncAttributeMaxDynamicSharedMemorySize, SMEM02);
        attr_done = true;
    }

    // Conversions + schedule build in one launch (last block builds).
    k_prep<<<NBLK + 1, 256>>>(
        (const float4*)x, (const float4*)w_in, w_ih, (const float4*)w_out, sp);

    // xproj: N=512 -> 4 tiles of 128; 64-row species subtiles (2 per sched tile)
    k_gemm<0><<<dim3(4, 2 * MAX_TILES), 128, SMEM02>>>(b_in, nullptr, nullptr);

    // gates (interleaved 3h+gate, fused LSTM): N=1536 -> 16 tiles of 96; 256 M-tiles
    k_gemm<1><<<dim3(16, NROWS / 64), 128, SMEM1>>>(b_ih, b_hh, out);

    // logits: N=1024 -> 8 tiles of 128; 64-row species subtiles
    k_gemm<2><<<dim3(8, 2 * MAX_TILES), 128, SMEM02>>>(b_out, nullptr, out);
}